// round 3
// baseline (speedup 1.0000x reference)
#include <cuda_runtime.h>
#include <cuda_bf16.h>
#include <mma.h>

using namespace nvcuda;

// Problem constants (fixed by the dataset)
#define NN 100000
#define FF 128
#define NC 40

// Scratch buffers: 3 x [N,128] fp32 (device globals; no allocation)
__device__ float g_bufA[NN * FF];
__device__ float g_bufB[NN * FF];
__device__ float g_bufC[NN * FF];

// ---------------------------------------------------------------------------
// out[i] = (1 + *eps) * in[i]   (vectorized float4)
// ---------------------------------------------------------------------------
__global__ void scale_copy(const float4* __restrict__ in, const float* __restrict__ eps,
                           float4* __restrict__ out, int n4) {
    int i = blockIdx.x * blockDim.x + threadIdx.x;
    if (i < n4) {
        float s = 1.0f + *eps;
        float4 v = in[i];
        v.x *= s; v.y *= s; v.z *= s; v.w *= s;
        out[i] = v;
    }
}

// ---------------------------------------------------------------------------
// Edge kernel: aggr[dst[e]] += relu(x[src[e]] + ea[e]*We + be)
// Warp-per-edge, indices staged 32/warp and broadcast, red.global.add.v4.f32.
// ---------------------------------------------------------------------------
__global__ void __launch_bounds__(256) edge_msg(
    const float4* __restrict__ x,           // [N, 32] float4 view of [N,128]
    const int* __restrict__ ei,             // [2, E] int32
    const float* __restrict__ ea,           // [E]
    const float* __restrict__ We,           // [128]
    const float* __restrict__ be,           // [128]
    float* __restrict__ aggr,               // [N, 128]
    int E)
{
    const int lane = threadIdx.x & 31;
    const int warp_global = (blockIdx.x * blockDim.x + threadIdx.x) >> 5;
    const int warp_stride = (gridDim.x * blockDim.x) >> 5;
    const int nchunk = (E + 31) / 32;

    const float4 we4 = ((const float4*)We)[lane];
    const float4 be4 = ((const float4*)be)[lane];

    for (int chunk = warp_global; chunk < nchunk; chunk += warp_stride) {
        int e = chunk * 32 + lane;
        int s = 0, d = 0;
        float a = 0.0f;
        if (e < E) {
            s = ei[e];
            d = ei[E + e];
            a = ea[e];
        }
        int cnt = E - chunk * 32;
        if (cnt > 32) cnt = 32;
        for (int j = 0; j < cnt; j++) {
            int sj = __shfl_sync(0xffffffffu, s, j);
            int dj = __shfl_sync(0xffffffffu, d, j);
            float aj = __shfl_sync(0xffffffffu, a, j);

            float4 xv = x[(long long)sj * 32 + lane];
            float4 m;
            m.x = fmaxf(fmaf(aj, we4.x, xv.x + be4.x), 0.0f);
            m.y = fmaxf(fmaf(aj, we4.y, xv.y + be4.y), 0.0f);
            m.z = fmaxf(fmaf(aj, we4.z, xv.z + be4.z), 0.0f);
            m.w = fmaxf(fmaf(aj, we4.w, xv.w + be4.w), 0.0f);

            float* p = aggr + ((long long)dj * 128 + lane * 4);
            asm volatile("red.global.add.v4.f32 [%0], {%1, %2, %3, %4};"
                         :: "l"(p), "f"(m.x), "f"(m.y), "f"(m.z), "f"(m.w)
                         : "memory");
        }
    }
}

// ---------------------------------------------------------------------------
// Tensor-core GEMM with tf32x2 compensation (error ~2^-22, ~fp32 quality):
//   C[M,128] = act(A[M,128] @ W[128,128] + bias)
//   if SCALED: also D = (1 + *eps) * C   (fuses the next layer's scale_copy)
// CTA: 128m x 128n tile, BK=32, 8 warps (4m x 2n), wmma m16n16k8 tf32.
// ---------------------------------------------------------------------------
template <bool RELU, bool SCALED>
__global__ void __launch_bounds__(256) gemm_tc(
    const float* __restrict__ A, const float* __restrict__ W,
    const float* __restrict__ bias, float* __restrict__ C,
    const float* __restrict__ eps, float* __restrict__ D, int M)
{
    __shared__ float sA[128][36];      // A chunk [m][k], padded
    __shared__ float sW[32][132];      // W chunk [k][n], padded
    __shared__ float sS[8][16 * 20];   // per-warp epilogue scratch (16x16, ldm 20)

    const int tid = threadIdx.x;
    const int wid = tid >> 5;
    const int lane = tid & 31;
    const int r0 = blockIdx.x * 128;
    const int wm = (wid & 3) * 32;     // warp m-offset
    const int wn = (wid >> 2) * 64;    // warp n-offset

    wmma::fragment<wmma::accumulator, 16, 16, 8, float> acc[2][4];
#pragma unroll
    for (int i = 0; i < 2; i++)
#pragma unroll
        for (int j = 0; j < 4; j++) wmma::fill_fragment(acc[i][j], 0.0f);

    for (int kb = 0; kb < 128; kb += 32) {
        // Load A chunk 128x32 (float4, coalesced). OOB rows clamped to r0.
#pragma unroll
        for (int i = 0; i < 4; i++) {
            int idx = tid + i * 256;
            int m = idx >> 3, k4 = idx & 7;
            int gr = r0 + m;
            if (gr >= M) gr = r0;
            float4 v = *(const float4*)(A + (size_t)gr * 128 + kb + k4 * 4);
            *(float4*)&sA[m][k4 * 4] = v;
        }
        // Load W chunk 32x128
#pragma unroll
        for (int i = 0; i < 4; i++) {
            int idx = tid + i * 256;
            int k = idx >> 5, n4 = idx & 31;
            float4 v = *(const float4*)(W + (size_t)(kb + k) * 128 + n4 * 4);
            *(float4*)&sW[k][n4 * 4] = v;
        }
        __syncthreads();

#pragma unroll
        for (int ks = 0; ks < 4; ks++) {
            wmma::fragment<wmma::matrix_a, 16, 16, 8, wmma::precision::tf32, wmma::row_major> ah[2], al[2];
#pragma unroll
            for (int im = 0; im < 2; im++) {
                wmma::load_matrix_sync(ah[im], &sA[wm + im * 16][ks * 8], 36);
#pragma unroll
                for (int t = 0; t < ah[im].num_elements; t++) {
                    float v = ah[im].x[t];
                    float h = wmma::__float_to_tf32(v);
                    ah[im].x[t] = h;
                    al[im].x[t] = wmma::__float_to_tf32(v - h);
                }
            }
#pragma unroll
            for (int in = 0; in < 4; in++) {
                wmma::fragment<wmma::matrix_b, 16, 16, 8, wmma::precision::tf32, wmma::row_major> bh, blo;
                wmma::load_matrix_sync(bh, &sW[ks * 8][wn + in * 16], 132);
#pragma unroll
                for (int t = 0; t < bh.num_elements; t++) {
                    float v = bh.x[t];
                    float h = wmma::__float_to_tf32(v);
                    bh.x[t] = h;
                    blo.x[t] = wmma::__float_to_tf32(v - h);
                }
#pragma unroll
                for (int im = 0; im < 2; im++) {
                    wmma::mma_sync(acc[im][in], ah[im], bh, acc[im][in]);
                    wmma::mma_sync(acc[im][in], ah[im], blo, acc[im][in]);
                    wmma::mma_sync(acc[im][in], al[im], bh, acc[im][in]);
                }
            }
        }
        __syncthreads();
    }

    float sc = 1.0f;
    if (SCALED) sc = 1.0f + *eps;

    // Epilogue: stage each 16x16 tile through per-warp smem scratch
#pragma unroll
    for (int im = 0; im < 2; im++) {
#pragma unroll
        for (int in = 0; in < 4; in++) {
            wmma::store_matrix_sync(&sS[wid][0], acc[im][in], 20, wmma::mem_row_major);
            __syncwarp();
            int row = lane >> 2;    // 0..7
            int c4 = lane & 3;      // 0..3
            int ncol = wn + in * 16 + c4 * 4;
            float4 bb = *(const float4*)(bias + ncol);
#pragma unroll
            for (int h = 0; h < 2; h++) {
                int r = row + h * 8;
                int gr = r0 + wm + im * 16 + r;
                if (gr < M) {
                    float4 v = *(float4*)&sS[wid][r * 20 + c4 * 4];
                    v.x += bb.x; v.y += bb.y; v.z += bb.z; v.w += bb.w;
                    if (RELU) {
                        v.x = fmaxf(v.x, 0.f); v.y = fmaxf(v.y, 0.f);
                        v.z = fmaxf(v.z, 0.f); v.w = fmaxf(v.w, 0.f);
                    }
                    *(float4*)(C + (size_t)gr * 128 + ncol) = v;
                    if (SCALED) {
                        float4 s4;
                        s4.x = v.x * sc; s4.y = v.y * sc; s4.z = v.z * sc; s4.w = v.w * sc;
                        *(float4*)(D + (size_t)gr * 128 + ncol) = s4;
                    }
                }
            }
            __syncwarp();
        }
    }
}

// ---------------------------------------------------------------------------
// out[n, :] = log_softmax(H[n, :] @ Wl + bl)   H:[N,128], Wl:[128,40]
// ---------------------------------------------------------------------------
__global__ void __launch_bounds__(256) classify_lsm(
    const float* __restrict__ H, const float* __restrict__ Wl,
    const float* __restrict__ bl, float* __restrict__ out, int M)
{
    __shared__ float sW[128 * NC];
    __shared__ float sb[NC];
    __shared__ float sh[32 * 129];
    __shared__ float sl[32 * NC];

    const int tid = threadIdx.x;
    const int r0 = blockIdx.x * 32;

    for (int i = tid; i < 128 * NC; i += 256) sW[i] = Wl[i];
    if (tid < NC) sb[tid] = bl[tid];
    for (int i = tid; i < 32 * 128; i += 256) {
        int row = i >> 7, col = i & 127;
        int gr = r0 + row;
        sh[row * 129 + col] = (gr < M) ? H[(long long)gr * 128 + col] : 0.0f;
    }
    __syncthreads();

#pragma unroll
    for (int t = 0; t < 5; t++) {
        int idx = tid + t * 256;
        int row = idx / NC, col = idx % NC;
        float acc = sb[col];
#pragma unroll 8
        for (int k = 0; k < 128; k++)
            acc = fmaf(sh[row * 129 + k], sW[k * NC + col], acc);
        sl[row * NC + col] = acc;
    }
    __syncthreads();

    if (tid < 32) {
        int row = tid;
        int gr = r0 + row;
        if (gr < M) {
            float mx = -1e30f;
            for (int c = 0; c < NC; c++) mx = fmaxf(mx, sl[row * NC + c]);
            float sum = 0.0f;
            for (int c = 0; c < NC; c++) sum += expf(sl[row * NC + c] - mx);
            float lse = mx + logf(sum);
            for (int c = 0; c < NC; c++)
                out[(long long)gr * NC + c] = sl[row * NC + c] - lse;
        }
    }
}

// ---------------------------------------------------------------------------
extern "C" void kernel_launch(void* const* d_in, const int* in_sizes, int n_in,
                              void* d_out, int out_size)
{
    const float* x    = (const float*)d_in[0];
    const int*   ei   = (const int*)d_in[1];      // int32 (JAX x64 disabled)
    const float* ea   = (const float*)d_in[2];
    const float* eps1 = (const float*)d_in[3];
    const float* We1  = (const float*)d_in[4];
    const float* be1  = (const float*)d_in[5];
    const float* W11  = (const float*)d_in[6];
    const float* b11  = (const float*)d_in[7];
    const float* W12  = (const float*)d_in[8];
    const float* b12  = (const float*)d_in[9];
    const float* eps2 = (const float*)d_in[10];
    const float* We2  = (const float*)d_in[11];
    const float* be2  = (const float*)d_in[12];
    const float* W21  = (const float*)d_in[13];
    const float* b21  = (const float*)d_in[14];
    const float* W22  = (const float*)d_in[15];
    const float* b22  = (const float*)d_in[16];
    const float* Wl   = (const float*)d_in[17];
    const float* bl   = (const float*)d_in[18];
    float* out = (float*)d_out;

    const int N = NN;
    const int E = in_sizes[2];

    float *A, *B, *C;
    cudaGetSymbolAddress((void**)&A, g_bufA);
    cudaGetSymbolAddress((void**)&B, g_bufB);
    cudaGetSymbolAddress((void**)&C, g_bufC);

    const int n4 = N * FF / 4;
    const int scale_blocks = (n4 + 255) / 256;
    const int edge_blocks = ((E + 31) / 32 + 7) / 8;
    const int gemm_blocks = (N + 127) / 128;
    const int cls_blocks = (N + 31) / 32;

    // ---- Layer 1 ----
    scale_copy<<<scale_blocks, 256>>>((const float4*)x, eps1, (float4*)A, n4);
    edge_msg<<<edge_blocks, 256>>>((const float4*)x, ei, ea, We1, be1, A, E);
    gemm_tc<true, false><<<gemm_blocks, 256>>>(A, W11, b11, B, nullptr, nullptr, N);
    // outer relu fused; also emit (1+eps2)*h into A (layer-2 aggr init)
    gemm_tc<true, true><<<gemm_blocks, 256>>>(B, W12, b12, C, eps2, A, N);

    // ---- Layer 2 ----
    edge_msg<<<edge_blocks, 256>>>((const float4*)C, ei, ea, We2, be2, A, E);
    gemm_tc<true, false><<<gemm_blocks, 256>>>(A, W21, b21, B, nullptr, nullptr, N);
    gemm_tc<true, false><<<gemm_blocks, 256>>>(B, W22, b22, C, nullptr, nullptr, N);

    // ---- Classifier + log_softmax ----
    classify_lsm<<<cls_blocks, 256>>>(C, Wl, bl, out, N);
}

// round 4
// speedup vs baseline: 1.3139x; 1.3139x over previous
#include <cuda_runtime.h>
#include <cuda_bf16.h>

// Problem constants (fixed by the dataset)
#define NN 100000
#define EE 1600000
#define FF 128
#define NC 40
#define SCAN_B 512
#define SCAN_NB ((NN + SCAN_B - 1) / SCAN_B)   // 196

// Scratch (device globals; no allocation)
__device__ float g_bufA[NN * FF];
__device__ float g_bufB[NN * FF];
__device__ float g_bufC[NN * FF];
__device__ int   g_deg[NN];
__device__ int   g_excl[NN];
__device__ int   g_btot[SCAN_NB];
__device__ int   g_off[NN + 1];
__device__ int   g_cur[NN];
__device__ int2  g_se[EE];       // packed {src, bitcast(ea)} sorted by dst

// ---------------------------------------------------------------------------
// Sort pipeline: counting sort of edges by dst
// ---------------------------------------------------------------------------
__global__ void zero_int(int* p, int n) {
    int i = blockIdx.x * blockDim.x + threadIdx.x;
    if (i < n) p[i] = 0;
}

__global__ void count_deg(const int* __restrict__ ei, int* __restrict__ deg, int E) {
    int e = blockIdx.x * blockDim.x + threadIdx.x;
    if (e < E) atomicAdd(&deg[ei[E + e]], 1);
}

__global__ void scan1(const int* __restrict__ deg, int* __restrict__ excl,
                      int* __restrict__ btot, int n) {
    __shared__ int sm[SCAN_B];
    int i = blockIdx.x * SCAN_B + threadIdx.x;
    int v = (i < n) ? deg[i] : 0;
    sm[threadIdx.x] = v;
    __syncthreads();
    for (int off = 1; off < SCAN_B; off <<= 1) {
        int t = (threadIdx.x >= off) ? sm[threadIdx.x - off] : 0;
        __syncthreads();
        sm[threadIdx.x] += t;
        __syncthreads();
    }
    int incl = sm[threadIdx.x];
    if (i < n) excl[i] = incl - v;
    if (threadIdx.x == SCAN_B - 1) btot[blockIdx.x] = incl;
}

__global__ void scan2(int* __restrict__ btot, int nb) {
    if (threadIdx.x == 0 && blockIdx.x == 0) {
        int run = 0;
        for (int b = 0; b < nb; b++) { int t = btot[b]; btot[b] = run; run += t; }
    }
}

__global__ void scan3(const int* __restrict__ excl, const int* __restrict__ btot,
                      int* __restrict__ off, int* __restrict__ cur, int n, int E) {
    int i = blockIdx.x * SCAN_B + threadIdx.x;
    if (i < n) {
        int o = excl[i] + btot[blockIdx.x];
        off[i] = o;
        cur[i] = o;
    }
    if (i == n) off[n] = E;
}

__global__ void scatter_edges(const int* __restrict__ ei, const float* __restrict__ ea,
                              int* __restrict__ cur, int2* __restrict__ se, int E) {
    int e = blockIdx.x * blockDim.x + threadIdx.x;
    if (e < E) {
        int src = ei[e];
        int dst = ei[E + e];
        int p = atomicAdd(&cur[dst], 1);
        se[p] = make_int2(src, __float_as_int(ea[e]));
    }
}

// ---------------------------------------------------------------------------
// Pull aggregation, no atomics: warp-per-node over CSR segment.
// aggr[n] = (1+eps)*x[n] + sum_{e in seg(n)} relu(x[src_e] + ea_e*We + be)
// ---------------------------------------------------------------------------
__global__ void __launch_bounds__(256) aggregate(
    const float4* __restrict__ x,          // [N,32] float4 view
    const int2* __restrict__ se,           // sorted {src, ea}
    const int* __restrict__ off,           // [N+1]
    const float* __restrict__ eps,
    const float* __restrict__ We,          // [128]
    const float* __restrict__ be,          // [128]
    float4* __restrict__ aggr,             // [N,32] float4 view
    int N)
{
    const int lane = threadIdx.x & 31;
    const int node = (blockIdx.x * blockDim.x + threadIdx.x) >> 5;
    if (node >= N) return;

    const float4 we4 = ((const float4*)We)[lane];
    const float4 be4 = ((const float4*)be)[lane];

    int start = off[node];
    int end = off[node + 1];

    float s = 1.0f + *eps;
    float4 acc = x[(size_t)node * 32 + lane];
    acc.x *= s; acc.y *= s; acc.z *= s; acc.w *= s;

    // software pipeline: prefetch next edge record while processing current
    int2 p;
    if (start < end) p = __ldg(&se[start]);
    for (int e = start; e < end; e++) {
        int src = p.x;
        float a = __int_as_float(p.y);
        if (e + 1 < end) p = __ldg(&se[e + 1]);
        float4 xv = x[(size_t)src * 32 + lane];
        acc.x += fmaxf(fmaf(a, we4.x, xv.x + be4.x), 0.0f);
        acc.y += fmaxf(fmaf(a, we4.y, xv.y + be4.y), 0.0f);
        acc.z += fmaxf(fmaf(a, we4.z, xv.z + be4.z), 0.0f);
        acc.w += fmaxf(fmaf(a, we4.w, xv.w + be4.w), 0.0f);
    }
    aggr[(size_t)node * 32 + lane] = acc;
}

// ---------------------------------------------------------------------------
// SIMT GEMM (proven round-2 version): C[M,128] = act(A @ W + bias)
// ---------------------------------------------------------------------------
template <bool RELU>
__global__ void __launch_bounds__(256) gemm128(
    const float* __restrict__ A, const float* __restrict__ W,
    const float* __restrict__ bias, float* __restrict__ C, int M)
{
    __shared__ float As[8][128];
    __shared__ float Bs[8][128];

    const int tid = threadIdx.x;
    const int r0 = blockIdx.x * 128;
    const int tx = tid & 15;
    const int ty = tid >> 4;

    const int arow = tid >> 1;
    const int ahalf = tid & 1;
    const int bk = tid >> 5;
    const int bc = (tid & 31) * 4;

    float acc[8][8];
#pragma unroll
    for (int i = 0; i < 8; i++)
#pragma unroll
        for (int j = 0; j < 8; j++) acc[i][j] = 0.0f;

    for (int kb = 0; kb < 128; kb += 8) {
        float4 av = make_float4(0.f, 0.f, 0.f, 0.f);
        int gr = r0 + arow;
        if (gr < M) av = *(const float4*)(A + (size_t)gr * 128 + kb + ahalf * 4);
        As[ahalf * 4 + 0][arow] = av.x;
        As[ahalf * 4 + 1][arow] = av.y;
        As[ahalf * 4 + 2][arow] = av.z;
        As[ahalf * 4 + 3][arow] = av.w;

        float4 bv = *(const float4*)(W + (size_t)(kb + bk) * 128 + bc);
        *(float4*)(&Bs[bk][bc]) = bv;

        __syncthreads();

#pragma unroll
        for (int k = 0; k < 8; k++) {
            float4 a0 = *(const float4*)(&As[k][ty * 8]);
            float4 a1 = *(const float4*)(&As[k][ty * 8 + 4]);
            float4 b0 = *(const float4*)(&Bs[k][tx * 8]);
            float4 b1 = *(const float4*)(&Bs[k][tx * 8 + 4]);
            float ra[8] = {a0.x, a0.y, a0.z, a0.w, a1.x, a1.y, a1.z, a1.w};
            float rb[8] = {b0.x, b0.y, b0.z, b0.w, b1.x, b1.y, b1.z, b1.w};
#pragma unroll
            for (int i = 0; i < 8; i++)
#pragma unroll
                for (int j = 0; j < 8; j++)
                    acc[i][j] = fmaf(ra[i], rb[j], acc[i][j]);
        }
        __syncthreads();
    }

    float4 bv0 = *(const float4*)(bias + tx * 8);
    float4 bv1 = *(const float4*)(bias + tx * 8 + 4);
    float bb[8] = {bv0.x, bv0.y, bv0.z, bv0.w, bv1.x, bv1.y, bv1.z, bv1.w};

#pragma unroll
    for (int i = 0; i < 8; i++) {
        int gr = r0 + ty * 8 + i;
        if (gr >= M) continue;
#pragma unroll
        for (int j = 0; j < 8; j += 4) {
            float4 o;
            o.x = acc[i][j + 0] + bb[j + 0];
            o.y = acc[i][j + 1] + bb[j + 1];
            o.z = acc[i][j + 2] + bb[j + 2];
            o.w = acc[i][j + 3] + bb[j + 3];
            if (RELU) {
                o.x = fmaxf(o.x, 0.f); o.y = fmaxf(o.y, 0.f);
                o.z = fmaxf(o.z, 0.f); o.w = fmaxf(o.w, 0.f);
            }
            *(float4*)(C + (size_t)gr * 128 + tx * 8 + j) = o;
        }
    }
}

// ---------------------------------------------------------------------------
// out[n, :] = log_softmax(H[n, :] @ Wl + bl)
// ---------------------------------------------------------------------------
__global__ void __launch_bounds__(256) classify_lsm(
    const float* __restrict__ H, const float* __restrict__ Wl,
    const float* __restrict__ bl, float* __restrict__ out, int M)
{
    __shared__ float sW[128 * NC];
    __shared__ float sb[NC];
    __shared__ float sh[32 * 129];
    __shared__ float sl[32 * NC];

    const int tid = threadIdx.x;
    const int r0 = blockIdx.x * 32;

    for (int i = tid; i < 128 * NC; i += 256) sW[i] = Wl[i];
    if (tid < NC) sb[tid] = bl[tid];
    for (int i = tid; i < 32 * 128; i += 256) {
        int row = i >> 7, col = i & 127;
        int gr = r0 + row;
        sh[row * 129 + col] = (gr < M) ? H[(size_t)gr * 128 + col] : 0.0f;
    }
    __syncthreads();

#pragma unroll
    for (int t = 0; t < 5; t++) {
        int idx = tid + t * 256;
        int row = idx / NC, col = idx % NC;
        float acc = sb[col];
#pragma unroll 8
        for (int k = 0; k < 128; k++)
            acc = fmaf(sh[row * 129 + k], sW[k * NC + col], acc);
        sl[row * NC + col] = acc;
    }
    __syncthreads();

    if (tid < 32) {
        int row = tid;
        int gr = r0 + row;
        if (gr < M) {
            float mx = -1e30f;
            for (int c = 0; c < NC; c++) mx = fmaxf(mx, sl[row * NC + c]);
            float sum = 0.0f;
            for (int c = 0; c < NC; c++) sum += expf(sl[row * NC + c] - mx);
            float lse = mx + logf(sum);
            for (int c = 0; c < NC; c++)
                out[(size_t)gr * NC + c] = sl[row * NC + c] - lse;
        }
    }
}

// ---------------------------------------------------------------------------
extern "C" void kernel_launch(void* const* d_in, const int* in_sizes, int n_in,
                              void* d_out, int out_size)
{
    const float* x    = (const float*)d_in[0];
    const int*   ei   = (const int*)d_in[1];      // int32 (JAX x64 disabled)
    const float* ea   = (const float*)d_in[2];
    const float* eps1 = (const float*)d_in[3];
    const float* We1  = (const float*)d_in[4];
    const float* be1  = (const float*)d_in[5];
    const float* W11  = (const float*)d_in[6];
    const float* b11  = (const float*)d_in[7];
    const float* W12  = (const float*)d_in[8];
    const float* b12  = (const float*)d_in[9];
    const float* eps2 = (const float*)d_in[10];
    const float* We2  = (const float*)d_in[11];
    const float* be2  = (const float*)d_in[12];
    const float* W21  = (const float*)d_in[13];
    const float* b21  = (const float*)d_in[14];
    const float* W22  = (const float*)d_in[15];
    const float* b22  = (const float*)d_in[16];
    const float* Wl   = (const float*)d_in[17];
    const float* bl   = (const float*)d_in[18];
    float* out = (float*)d_out;

    const int N = NN;
    const int E = in_sizes[2];

    float *A, *B, *C;
    int *deg, *excl, *btot, *off, *cur;
    int2 *se;
    cudaGetSymbolAddress((void**)&A, g_bufA);
    cudaGetSymbolAddress((void**)&B, g_bufB);
    cudaGetSymbolAddress((void**)&C, g_bufC);
    cudaGetSymbolAddress((void**)&deg, g_deg);
    cudaGetSymbolAddress((void**)&excl, g_excl);
    cudaGetSymbolAddress((void**)&btot, g_btot);
    cudaGetSymbolAddress((void**)&off, g_off);
    cudaGetSymbolAddress((void**)&cur, g_cur);
    cudaGetSymbolAddress((void**)&se, g_se);

    const int eb = (E + 255) / 256;
    const int nb = (N + 255) / 256;
    const int gemm_blocks = (N + 127) / 128;
    const int cls_blocks = (N + 31) / 32;
    const int agg_blocks = (N * 32 + 255) / 256;   // warp per node

    // ---- One-time counting sort of edges by dst ----
    zero_int<<<nb, 256>>>(deg, N);
    count_deg<<<eb, 256>>>(ei, deg, E);
    scan1<<<SCAN_NB, SCAN_B>>>(deg, excl, btot, N);
    scan2<<<1, 32>>>(btot, SCAN_NB);
    scan3<<<SCAN_NB, SCAN_B>>>(excl, btot, off, cur, N, E);
    scatter_edges<<<eb, 256>>>(ei, ea, cur, se, E);

    // ---- Layer 1 ----
    aggregate<<<agg_blocks, 256>>>((const float4*)x, se, off, eps1, We1, be1,
                                   (float4*)A, N);
    gemm128<true><<<gemm_blocks, 256>>>(A, W11, b11, B, N);
    gemm128<true><<<gemm_blocks, 256>>>(B, W12, b12, C, N);   // outer relu fused

    // ---- Layer 2 ----
    aggregate<<<agg_blocks, 256>>>((const float4*)C, se, off, eps2, We2, be2,
                                   (float4*)B, N);
    gemm128<true><<<gemm_blocks, 256>>>(B, W21, b21, A, N);
    gemm128<true><<<gemm_blocks, 256>>>(A, W22, b22, B, N);   // outer relu fused

    // ---- Classifier + log_softmax ----
    classify_lsm<<<cls_blocks, 256>>>(B, Wl, bl, out, N);
}

// round 5
// speedup vs baseline: 1.3300x; 1.0122x over previous
#include <cuda_runtime.h>
#include <cuda_bf16.h>

// Problem constants (fixed by the dataset)
#define NN 100000
#define EE 1600000
#define FF 128
#define NC 40
#define SCAN_B 512
#define SCAN_NB ((NN + SCAN_B - 1) / SCAN_B)   // 196

// Scratch (device globals; no allocation)
__device__ float g_bufA[NN * FF];
__device__ float g_bufB[NN * FF];
__device__ float g_bufC[NN * FF];
__device__ int   g_deg[NN];
__device__ int   g_excl[NN];
__device__ int   g_btot[SCAN_NB];
__device__ int   g_off[NN + 1];
__device__ int   g_cur[NN];
__device__ int2  g_se[EE];       // packed {src, bitcast(ea)} sorted by dst

typedef unsigned long long ull;

// packed f32x2 helpers (sm_100a: FFMA2 only reachable via PTX fma.rn.f32x2)
__device__ __forceinline__ ull pack2(float v) {
    ull r;
    asm("mov.b64 %0, {%1, %1};" : "=l"(r) : "f"(v));
    return r;
}
__device__ __forceinline__ void fma2(ull& acc, ull a, ull b) {
    asm("fma.rn.f32x2 %0, %1, %2, %0;" : "+l"(acc) : "l"(a), "l"(b));
}

// ---------------------------------------------------------------------------
// Sort pipeline: counting sort of edges by dst
// ---------------------------------------------------------------------------
__global__ void zero_int(int* p, int n) {
    int i = blockIdx.x * blockDim.x + threadIdx.x;
    if (i < n) p[i] = 0;
}

__global__ void count_deg(const int* __restrict__ ei, int* __restrict__ deg, int E) {
    int e = blockIdx.x * blockDim.x + threadIdx.x;
    if (e < E) atomicAdd(&deg[ei[E + e]], 1);
}

__global__ void scan1(const int* __restrict__ deg, int* __restrict__ excl,
                      int* __restrict__ btot, int n) {
    __shared__ int sm[SCAN_B];
    int i = blockIdx.x * SCAN_B + threadIdx.x;
    int v = (i < n) ? deg[i] : 0;
    sm[threadIdx.x] = v;
    __syncthreads();
    for (int off = 1; off < SCAN_B; off <<= 1) {
        int t = (threadIdx.x >= off) ? sm[threadIdx.x - off] : 0;
        __syncthreads();
        sm[threadIdx.x] += t;
        __syncthreads();
    }
    int incl = sm[threadIdx.x];
    if (i < n) excl[i] = incl - v;
    if (threadIdx.x == SCAN_B - 1) btot[blockIdx.x] = incl;
}

// parallel exclusive scan of the 196 block totals (single block)
__global__ void scan2(int* __restrict__ btot, int nb) {
    __shared__ int sm[256];
    int t = threadIdx.x;
    int v = (t < nb) ? btot[t] : 0;
    sm[t] = v;
    __syncthreads();
    for (int off = 1; off < 256; off <<= 1) {
        int u = (t >= off) ? sm[t - off] : 0;
        __syncthreads();
        sm[t] += u;
        __syncthreads();
    }
    if (t < nb) btot[t] = sm[t] - v;
}

__global__ void scan3(const int* __restrict__ excl, const int* __restrict__ btot,
                      int* __restrict__ off, int* __restrict__ cur, int n, int E) {
    int i = blockIdx.x * SCAN_B + threadIdx.x;
    if (i < n) {
        int o = excl[i] + btot[blockIdx.x];
        off[i] = o;
        cur[i] = o;
    }
    if (i == n) off[n] = E;
}

__global__ void scatter_edges(const int* __restrict__ ei, const float* __restrict__ ea,
                              int* __restrict__ cur, int2* __restrict__ se, int E) {
    int e = blockIdx.x * blockDim.x + threadIdx.x;
    if (e < E) {
        int src = ei[e];
        int dst = ei[E + e];
        int p = atomicAdd(&cur[dst], 1);
        se[p] = make_int2(src, __float_as_int(ea[e]));
    }
}

// ---------------------------------------------------------------------------
// Pull aggregation, no atomics: warp-per-node over CSR segment.
// aggr[n] = (1+eps)*x[n] + sum_{e in seg(n)} relu(x[src_e] + ea_e*We + be)
// ---------------------------------------------------------------------------
__global__ void __launch_bounds__(256) aggregate(
    const float4* __restrict__ x,          // [N,32] float4 view
    const int2* __restrict__ se,           // sorted {src, ea}
    const int* __restrict__ off,           // [N+1]
    const float* __restrict__ eps,
    const float* __restrict__ We,          // [128]
    const float* __restrict__ be,          // [128]
    float4* __restrict__ aggr,             // [N,32] float4 view
    int N)
{
    const int lane = threadIdx.x & 31;
    const int node = (blockIdx.x * blockDim.x + threadIdx.x) >> 5;
    if (node >= N) return;

    const float4 we4 = ((const float4*)We)[lane];
    const float4 be4 = ((const float4*)be)[lane];

    int start = off[node];
    int end = off[node + 1];

    float s = 1.0f + *eps;
    float4 acc = x[(size_t)node * 32 + lane];
    acc.x *= s; acc.y *= s; acc.z *= s; acc.w *= s;

    int2 p;
    if (start < end) p = __ldg(&se[start]);
    for (int e = start; e < end; e++) {
        int src = p.x;
        float a = __int_as_float(p.y);
        if (e + 1 < end) p = __ldg(&se[e + 1]);
        float4 xv = x[(size_t)src * 32 + lane];
        acc.x += fmaxf(fmaf(a, we4.x, xv.x + be4.x), 0.0f);
        acc.y += fmaxf(fmaf(a, we4.y, xv.y + be4.y), 0.0f);
        acc.z += fmaxf(fmaf(a, we4.z, xv.z + be4.z), 0.0f);
        acc.w += fmaxf(fmaf(a, we4.w, xv.w + be4.w), 0.0f);
    }
    aggr[(size_t)node * 32 + lane] = acc;
}

// ---------------------------------------------------------------------------
// SIMT GEMM with packed f32x2 FMA: C[M,128] = act(A @ W + bias)
// 128x128 tile, BK=8, 256 threads, 8x8 per thread (stored as 8x4 f32x2).
// ---------------------------------------------------------------------------
template <bool RELU>
__global__ void __launch_bounds__(256) gemm128(
    const float* __restrict__ A, const float* __restrict__ W,
    const float* __restrict__ bias, float* __restrict__ C, int M)
{
    __shared__ float As[8][128];
    __shared__ float Bs[8][128];

    const int tid = threadIdx.x;
    const int r0 = blockIdx.x * 128;
    const int tx = tid & 15;
    const int ty = tid >> 4;

    const int arow = tid >> 1;
    const int ahalf = tid & 1;
    const int bk = tid >> 5;
    const int bc = (tid & 31) * 4;

    ull acc[8][4];
#pragma unroll
    for (int i = 0; i < 8; i++)
#pragma unroll
        for (int j = 0; j < 4; j++) acc[i][j] = 0ull;

    for (int kb = 0; kb < 128; kb += 8) {
        float4 av = make_float4(0.f, 0.f, 0.f, 0.f);
        int gr = r0 + arow;
        if (gr < M) av = *(const float4*)(A + (size_t)gr * 128 + kb + ahalf * 4);
        As[ahalf * 4 + 0][arow] = av.x;
        As[ahalf * 4 + 1][arow] = av.y;
        As[ahalf * 4 + 2][arow] = av.z;
        As[ahalf * 4 + 3][arow] = av.w;

        float4 bv = *(const float4*)(W + (size_t)(kb + bk) * 128 + bc);
        *(float4*)(&Bs[bk][bc]) = bv;

        __syncthreads();

#pragma unroll
        for (int k = 0; k < 8; k++) {
            float4 a0 = *(const float4*)(&As[k][ty * 8]);
            float4 a1 = *(const float4*)(&As[k][ty * 8 + 4]);
            // B pairs as 64-bit lanes: (b0,b1)(b2,b3)(b4,b5)(b6,b7)
            ulonglong2 bp0 = *(const ulonglong2*)(&Bs[k][tx * 8]);
            ulonglong2 bp1 = *(const ulonglong2*)(&Bs[k][tx * 8 + 4]);
            ull rb[4] = {bp0.x, bp0.y, bp1.x, bp1.y};
            float ra[8] = {a0.x, a0.y, a0.z, a0.w, a1.x, a1.y, a1.z, a1.w};
#pragma unroll
            for (int i = 0; i < 8; i++) {
                ull ai = pack2(ra[i]);
#pragma unroll
                for (int j = 0; j < 4; j++)
                    fma2(acc[i][j], ai, rb[j]);
            }
        }
        __syncthreads();
    }

    float4 bv0 = *(const float4*)(bias + tx * 8);
    float4 bv1 = *(const float4*)(bias + tx * 8 + 4);
    float bb[8] = {bv0.x, bv0.y, bv0.z, bv0.w, bv1.x, bv1.y, bv1.z, bv1.w};

#pragma unroll
    for (int i = 0; i < 8; i++) {
        int gr = r0 + ty * 8 + i;
        if (gr >= M) continue;
#pragma unroll
        for (int j = 0; j < 8; j += 4) {
            float2 p0 = *(float2*)&acc[i][j / 2];
            float2 p1 = *(float2*)&acc[i][j / 2 + 1];
            float4 o;
            o.x = p0.x + bb[j + 0];
            o.y = p0.y + bb[j + 1];
            o.z = p1.x + bb[j + 2];
            o.w = p1.y + bb[j + 3];
            if (RELU) {
                o.x = fmaxf(o.x, 0.f); o.y = fmaxf(o.y, 0.f);
                o.z = fmaxf(o.z, 0.f); o.w = fmaxf(o.w, 0.f);
            }
            *(float4*)(C + (size_t)gr * 128 + tx * 8 + j) = o;
        }
    }
}

// ---------------------------------------------------------------------------
// out[n, :] = log_softmax(H[n, :] @ Wl + bl)
// ---------------------------------------------------------------------------
__global__ void __launch_bounds__(256) classify_lsm(
    const float* __restrict__ H, const float* __restrict__ Wl,
    const float* __restrict__ bl, float* __restrict__ out, int M)
{
    __shared__ float sW[128 * NC];
    __shared__ float sb[NC];
    __shared__ float sh[32 * 129];
    __shared__ float sl[32 * NC];

    const int tid = threadIdx.x;
    const int r0 = blockIdx.x * 32;

    for (int i = tid; i < 128 * NC; i += 256) sW[i] = Wl[i];
    if (tid < NC) sb[tid] = bl[tid];
    for (int i = tid; i < 32 * 128; i += 256) {
        int row = i >> 7, col = i & 127;
        int gr = r0 + row;
        sh[row * 129 + col] = (gr < M) ? H[(size_t)gr * 128 + col] : 0.0f;
    }
    __syncthreads();

#pragma unroll
    for (int t = 0; t < 5; t++) {
        int idx = tid + t * 256;
        int row = idx / NC, col = idx % NC;
        float acc = sb[col];
#pragma unroll 8
        for (int k = 0; k < 128; k++)
            acc = fmaf(sh[row * 129 + k], sW[k * NC + col], acc);
        sl[row * NC + col] = acc;
    }
    __syncthreads();

    if (tid < 32) {
        int row = tid;
        int gr = r0 + row;
        if (gr < M) {
            float mx = -1e30f;
            for (int c = 0; c < NC; c++) mx = fmaxf(mx, sl[row * NC + c]);
            float sum = 0.0f;
            for (int c = 0; c < NC; c++) sum += expf(sl[row * NC + c] - mx);
            float lse = mx + logf(sum);
            for (int c = 0; c < NC; c++)
                out[(size_t)gr * NC + c] = sl[row * NC + c] - lse;
        }
    }
}

// ---------------------------------------------------------------------------
extern "C" void kernel_launch(void* const* d_in, const int* in_sizes, int n_in,
                              void* d_out, int out_size)
{
    const float* x    = (const float*)d_in[0];
    const int*   ei   = (const int*)d_in[1];      // int32 (JAX x64 disabled)
    const float* ea   = (const float*)d_in[2];
    const float* eps1 = (const float*)d_in[3];
    const float* We1  = (const float*)d_in[4];
    const float* be1  = (const float*)d_in[5];
    const float* W11  = (const float*)d_in[6];
    const float* b11  = (const float*)d_in[7];
    const float* W12  = (const float*)d_in[8];
    const float* b12  = (const float*)d_in[9];
    const float* eps2 = (const float*)d_in[10];
    const float* We2  = (const float*)d_in[11];
    const float* be2  = (const float*)d_in[12];
    const float* W21  = (const float*)d_in[13];
    const float* b21  = (const float*)d_in[14];
    const float* W22  = (const float*)d_in[15];
    const float* b22  = (const float*)d_in[16];
    const float* Wl   = (const float*)d_in[17];
    const float* bl   = (const float*)d_in[18];
    float* out = (float*)d_out;

    const int N = NN;
    const int E = in_sizes[2];

    float *A, *B, *C;
    int *deg, *excl, *btot, *off, *cur;
    int2 *se;
    cudaGetSymbolAddress((void**)&A, g_bufA);
    cudaGetSymbolAddress((void**)&B, g_bufB);
    cudaGetSymbolAddress((void**)&C, g_bufC);
    cudaGetSymbolAddress((void**)&deg, g_deg);
    cudaGetSymbolAddress((void**)&excl, g_excl);
    cudaGetSymbolAddress((void**)&btot, g_btot);
    cudaGetSymbolAddress((void**)&off, g_off);
    cudaGetSymbolAddress((void**)&cur, g_cur);
    cudaGetSymbolAddress((void**)&se, g_se);

    const int eb = (E + 255) / 256;
    const int nb = (N + 255) / 256;
    const int gemm_blocks = (N + 127) / 128;
    const int cls_blocks = (N + 31) / 32;
    const int agg_blocks = (N * 32 + 255) / 256;   // warp per node

    // ---- One-time counting sort of edges by dst ----
    zero_int<<<nb, 256>>>(deg, N);
    count_deg<<<eb, 256>>>(ei, deg, E);
    scan1<<<SCAN_NB, SCAN_B>>>(deg, excl, btot, N);
    scan2<<<1, 256>>>(btot, SCAN_NB);
    scan3<<<SCAN_NB, SCAN_B>>>(excl, btot, off, cur, N, E);
    scatter_edges<<<eb, 256>>>(ei, ea, cur, se, E);

    // ---- Layer 1 ----
    aggregate<<<agg_blocks, 256>>>((const float4*)x, se, off, eps1, We1, be1,
                                   (float4*)A, N);
    gemm128<true><<<gemm_blocks, 256>>>(A, W11, b11, B, N);
    gemm128<true><<<gemm_blocks, 256>>>(B, W12, b12, C, N);   // outer relu fused

    // ---- Layer 2 ----
    aggregate<<<agg_blocks, 256>>>((const float4*)C, se, off, eps2, We2, be2,
                                   (float4*)B, N);
    gemm128<true><<<gemm_blocks, 256>>>(B, W21, b21, A, N);
    gemm128<true><<<gemm_blocks, 256>>>(A, W22, b22, B, N);   // outer relu fused

    // ---- Classifier + log_softmax ----
    classify_lsm<<<cls_blocks, 256>>>(B, Wl, bl, out, N);
}

// round 6
// speedup vs baseline: 1.4460x; 1.0873x over previous
#include <cuda_runtime.h>
#include <cuda_bf16.h>
#include <mma.h>

using namespace nvcuda;

// Problem constants (fixed by the dataset)
#define NN 100000
#define EE 1600000
#define FF 128
#define NC 40
#define SCAN_B 512
#define SCAN_NB ((NN + SCAN_B - 1) / SCAN_B)   // 196

// Scratch (device globals; no allocation)
__device__ float g_bufA[NN * FF];
__device__ float g_bufB[NN * FF];
__device__ float g_bufC[NN * FF];
__device__ int   g_deg[NN];
__device__ int   g_excl[NN];
__device__ int   g_btot[SCAN_NB];
__device__ int   g_off[NN + 1];
__device__ int   g_cur[NN];
__device__ int2  g_se[EE];       // packed {src, bitcast(ea)} sorted by dst

__device__ __forceinline__ void split_bf16(float v, __nv_bfloat16& h, __nv_bfloat16& l) {
    h = __float2bfloat16_rn(v);
    l = __float2bfloat16_rn(v - __bfloat162float(h));
}

// ---------------------------------------------------------------------------
// Sort pipeline: counting sort of edges by dst
// ---------------------------------------------------------------------------
__global__ void zero_int(int* p, int n) {
    int i = blockIdx.x * blockDim.x + threadIdx.x;
    if (i < n) p[i] = 0;
}

__global__ void count_deg(const int* __restrict__ ei, int* __restrict__ deg, int E) {
    int e = blockIdx.x * blockDim.x + threadIdx.x;
    if (e < E) atomicAdd(&deg[ei[E + e]], 1);
}

__global__ void scan1(const int* __restrict__ deg, int* __restrict__ excl,
                      int* __restrict__ btot, int n) {
    __shared__ int sm[SCAN_B];
    int i = blockIdx.x * SCAN_B + threadIdx.x;
    int v = (i < n) ? deg[i] : 0;
    sm[threadIdx.x] = v;
    __syncthreads();
    for (int off = 1; off < SCAN_B; off <<= 1) {
        int t = (threadIdx.x >= off) ? sm[threadIdx.x - off] : 0;
        __syncthreads();
        sm[threadIdx.x] += t;
        __syncthreads();
    }
    int incl = sm[threadIdx.x];
    if (i < n) excl[i] = incl - v;
    if (threadIdx.x == SCAN_B - 1) btot[blockIdx.x] = incl;
}

__global__ void scan2(int* __restrict__ btot, int nb) {
    __shared__ int sm[256];
    int t = threadIdx.x;
    int v = (t < nb) ? btot[t] : 0;
    sm[t] = v;
    __syncthreads();
    for (int off = 1; off < 256; off <<= 1) {
        int u = (t >= off) ? sm[t - off] : 0;
        __syncthreads();
        sm[t] += u;
        __syncthreads();
    }
    if (t < nb) btot[t] = sm[t] - v;
}

__global__ void scan3(const int* __restrict__ excl, const int* __restrict__ btot,
                      int* __restrict__ off, int* __restrict__ cur, int n, int E) {
    int i = blockIdx.x * SCAN_B + threadIdx.x;
    if (i < n) {
        int o = excl[i] + btot[blockIdx.x];
        off[i] = o;
        cur[i] = o;
    }
    if (i == n) off[n] = E;
}

__global__ void scatter_edges(const int* __restrict__ ei, const float* __restrict__ ea,
                              int* __restrict__ cur, int2* __restrict__ se, int E) {
    int e = blockIdx.x * blockDim.x + threadIdx.x;
    if (e < E) {
        int src = ei[e];
        int dst = ei[E + e];
        int p = atomicAdd(&cur[dst], 1);
        se[p] = make_int2(src, __float_as_int(ea[e]));
    }
}

// ---------------------------------------------------------------------------
// Pull aggregation, no atomics: warp-per-node over CSR segment.
// aggr[n] = (1+eps)*x[n] + sum_{e in seg(n)} relu(x[src_e] + ea_e*We + be)
// ---------------------------------------------------------------------------
__global__ void __launch_bounds__(256) aggregate(
    const float4* __restrict__ x,          // [N,32] float4 view
    const int2* __restrict__ se,           // sorted {src, ea}
    const int* __restrict__ off,           // [N+1]
    const float* __restrict__ eps,
    const float* __restrict__ We,          // [128]
    const float* __restrict__ be,          // [128]
    float4* __restrict__ aggr,             // [N,32] float4 view
    int N)
{
    const int lane = threadIdx.x & 31;
    const int node = (blockIdx.x * blockDim.x + threadIdx.x) >> 5;
    if (node >= N) return;

    const float4 we4 = ((const float4*)We)[lane];
    const float4 be4 = ((const float4*)be)[lane];

    int start = off[node];
    int end = off[node + 1];

    float s = 1.0f + *eps;
    float4 acc = x[(size_t)node * 32 + lane];
    acc.x *= s; acc.y *= s; acc.z *= s; acc.w *= s;

    int2 p;
    if (start < end) p = __ldg(&se[start]);
    for (int e = start; e < end; e++) {
        int src = p.x;
        float a = __int_as_float(p.y);
        if (e + 1 < end) p = __ldg(&se[e + 1]);
        float4 xv = x[(size_t)src * 32 + lane];
        acc.x += fmaxf(fmaf(a, we4.x, xv.x + be4.x), 0.0f);
        acc.y += fmaxf(fmaf(a, we4.y, xv.y + be4.y), 0.0f);
        acc.z += fmaxf(fmaf(a, we4.z, xv.z + be4.z), 0.0f);
        acc.w += fmaxf(fmaf(a, we4.w, xv.w + be4.w), 0.0f);
    }
    aggr[(size_t)node * 32 + lane] = acc;
}

// ---------------------------------------------------------------------------
// Tensor-core GEMM, bf16 hi/lo split (3 MMAs, ~2^-17 product error):
//   C[M,128] = act(A[M,128] @ W[128,128] + bias)
// CTA: 128m x 128n, BK=32 chunks, 8 warps (4m x 2n), wmma m16n16k16 bf16.
// Split conversion happens ONCE at smem fill, not in the MMA loop.
// ---------------------------------------------------------------------------
template <bool RELU>
__global__ void __launch_bounds__(256) gemm_bf(
    const float* __restrict__ A, const float* __restrict__ W,
    const float* __restrict__ bias, float* __restrict__ C, int M)
{
    __shared__ __nv_bfloat16 sAh[128][40];   // [m][k], pad 40
    __shared__ __nv_bfloat16 sAl[128][40];
    __shared__ __nv_bfloat16 sWh[32][136];   // [k][n], pad 136
    __shared__ __nv_bfloat16 sWl[32][136];

    const int tid = threadIdx.x;
    const int wid = tid >> 5;
    const int lane = tid & 31;
    const int r0 = blockIdx.x * 128;
    const int wm = (wid & 3) * 32;     // warp m-offset
    const int wn = (wid >> 2) * 64;    // warp n-offset

    wmma::fragment<wmma::accumulator, 16, 16, 16, float> acc[2][4];
#pragma unroll
    for (int i = 0; i < 2; i++)
#pragma unroll
        for (int j = 0; j < 4; j++) wmma::fill_fragment(acc[i][j], 0.0f);

    for (int kb = 0; kb < 128; kb += 32) {
        // A chunk 128x32: 1024 float4 over 256 threads, split-convert on store
#pragma unroll
        for (int i = 0; i < 4; i++) {
            int idx = tid + i * 256;
            int m = idx >> 3, k4 = idx & 7;
            int gr = r0 + m;
            if (gr >= M) gr = r0;
            float4 v = *(const float4*)(A + (size_t)gr * 128 + kb + k4 * 4);
            __nv_bfloat16 h, l;
            split_bf16(v.x, h, l); sAh[m][k4 * 4 + 0] = h; sAl[m][k4 * 4 + 0] = l;
            split_bf16(v.y, h, l); sAh[m][k4 * 4 + 1] = h; sAl[m][k4 * 4 + 1] = l;
            split_bf16(v.z, h, l); sAh[m][k4 * 4 + 2] = h; sAl[m][k4 * 4 + 2] = l;
            split_bf16(v.w, h, l); sAh[m][k4 * 4 + 3] = h; sAl[m][k4 * 4 + 3] = l;
        }
        // W chunk 32x128
#pragma unroll
        for (int i = 0; i < 4; i++) {
            int idx = tid + i * 256;
            int k = idx >> 5, n4 = idx & 31;
            float4 v = *(const float4*)(W + (size_t)(kb + k) * 128 + n4 * 4);
            __nv_bfloat16 h, l;
            split_bf16(v.x, h, l); sWh[k][n4 * 4 + 0] = h; sWl[k][n4 * 4 + 0] = l;
            split_bf16(v.y, h, l); sWh[k][n4 * 4 + 1] = h; sWl[k][n4 * 4 + 1] = l;
            split_bf16(v.z, h, l); sWh[k][n4 * 4 + 2] = h; sWl[k][n4 * 4 + 2] = l;
            split_bf16(v.w, h, l); sWh[k][n4 * 4 + 3] = h; sWl[k][n4 * 4 + 3] = l;
        }
        __syncthreads();

#pragma unroll
        for (int ks = 0; ks < 2; ks++) {
            wmma::fragment<wmma::matrix_a, 16, 16, 16, __nv_bfloat16, wmma::row_major> ah[2], al[2];
#pragma unroll
            for (int im = 0; im < 2; im++) {
                wmma::load_matrix_sync(ah[im], &sAh[wm + im * 16][ks * 16], 40);
                wmma::load_matrix_sync(al[im], &sAl[wm + im * 16][ks * 16], 40);
            }
#pragma unroll
            for (int in = 0; in < 4; in++) {
                wmma::fragment<wmma::matrix_b, 16, 16, 16, __nv_bfloat16, wmma::row_major> bh, bl;
                wmma::load_matrix_sync(bh, &sWh[ks * 16][wn + in * 16], 136);
                wmma::load_matrix_sync(bl, &sWl[ks * 16][wn + in * 16], 136);
#pragma unroll
                for (int im = 0; im < 2; im++) {
                    wmma::mma_sync(acc[im][in], ah[im], bh, acc[im][in]);
                    wmma::mma_sync(acc[im][in], ah[im], bl, acc[im][in]);
                    wmma::mma_sync(acc[im][in], al[im], bh, acc[im][in]);
                }
            }
        }
        __syncthreads();
    }

    // Epilogue: alias the A-tile smem as per-warp fp32 scratch (16x16, ldm 20)
    float* scratch = (float*)&sAh[0][0] + wid * 320;   // 8 warps * 320 floats = 10KB < 20KB

#pragma unroll
    for (int im = 0; im < 2; im++) {
#pragma unroll
        for (int in = 0; in < 4; in++) {
            wmma::store_matrix_sync(scratch, acc[im][in], 20, wmma::mem_row_major);
            __syncwarp();
            int row = lane >> 2;    // 0..7
            int c4 = lane & 3;      // 0..3
            int ncol = wn + in * 16 + c4 * 4;
            float4 bb = *(const float4*)(bias + ncol);
#pragma unroll
            for (int h = 0; h < 2; h++) {
                int r = row + h * 8;
                int gr = r0 + wm + im * 16 + r;
                if (gr < M) {
                    float4 v = *(float4*)&scratch[r * 20 + c4 * 4];
                    v.x += bb.x; v.y += bb.y; v.z += bb.z; v.w += bb.w;
                    if (RELU) {
                        v.x = fmaxf(v.x, 0.f); v.y = fmaxf(v.y, 0.f);
                        v.z = fmaxf(v.z, 0.f); v.w = fmaxf(v.w, 0.f);
                    }
                    *(float4*)(C + (size_t)gr * 128 + ncol) = v;
                }
            }
            __syncwarp();
        }
    }
}

// ---------------------------------------------------------------------------
// out[n, :] = log_softmax(H[n, :] @ Wl + bl)
// ---------------------------------------------------------------------------
__global__ void __launch_bounds__(256) classify_lsm(
    const float* __restrict__ H, const float* __restrict__ Wl,
    const float* __restrict__ bl, float* __restrict__ out, int M)
{
    __shared__ float sW[128 * NC];
    __shared__ float sb[NC];
    __shared__ float sh[32 * 129];
    __shared__ float sl[32 * NC];

    const int tid = threadIdx.x;
    const int r0 = blockIdx.x * 32;

    for (int i = tid; i < 128 * NC; i += 256) sW[i] = Wl[i];
    if (tid < NC) sb[tid] = bl[tid];
    for (int i = tid; i < 32 * 128; i += 256) {
        int row = i >> 7, col = i & 127;
        int gr = r0 + row;
        sh[row * 129 + col] = (gr < M) ? H[(size_t)gr * 128 + col] : 0.0f;
    }
    __syncthreads();

#pragma unroll
    for (int t = 0; t < 5; t++) {
        int idx = tid + t * 256;
        int row = idx / NC, col = idx % NC;
        float acc = sb[col];
#pragma unroll 8
        for (int k = 0; k < 128; k++)
            acc = fmaf(sh[row * 129 + k], sW[k * NC + col], acc);
        sl[row * NC + col] = acc;
    }
    __syncthreads();

    if (tid < 32) {
        int row = tid;
        int gr = r0 + row;
        if (gr < M) {
            float mx = -1e30f;
            for (int c = 0; c < NC; c++) mx = fmaxf(mx, sl[row * NC + c]);
            float sum = 0.0f;
            for (int c = 0; c < NC; c++) sum += expf(sl[row * NC + c] - mx);
            float lse = mx + logf(sum);
            for (int c = 0; c < NC; c++)
                out[(size_t)gr * NC + c] = sl[row * NC + c] - lse;
        }
    }
}

// ---------------------------------------------------------------------------
extern "C" void kernel_launch(void* const* d_in, const int* in_sizes, int n_in,
                              void* d_out, int out_size)
{
    const float* x    = (const float*)d_in[0];
    const int*   ei   = (const int*)d_in[1];      // int32 (JAX x64 disabled)
    const float* ea   = (const float*)d_in[2];
    const float* eps1 = (const float*)d_in[3];
    const float* We1  = (const float*)d_in[4];
    const float* be1  = (const float*)d_in[5];
    const float* W11  = (const float*)d_in[6];
    const float* b11  = (const float*)d_in[7];
    const float* W12  = (const float*)d_in[8];
    const float* b12  = (const float*)d_in[9];
    const float* eps2 = (const float*)d_in[10];
    const float* We2  = (const float*)d_in[11];
    const float* be2  = (const float*)d_in[12];
    const float* W21  = (const float*)d_in[13];
    const float* b21  = (const float*)d_in[14];
    const float* W22  = (const float*)d_in[15];
    const float* b22  = (const float*)d_in[16];
    const float* Wl   = (const float*)d_in[17];
    const float* bl   = (const float*)d_in[18];
    float* out = (float*)d_out;

    const int N = NN;
    const int E = in_sizes[2];

    float *A, *B, *C;
    int *deg, *excl, *btot, *off, *cur;
    int2 *se;
    cudaGetSymbolAddress((void**)&A, g_bufA);
    cudaGetSymbolAddress((void**)&B, g_bufB);
    cudaGetSymbolAddress((void**)&C, g_bufC);
    cudaGetSymbolAddress((void**)&deg, g_deg);
    cudaGetSymbolAddress((void**)&excl, g_excl);
    cudaGetSymbolAddress((void**)&btot, g_btot);
    cudaGetSymbolAddress((void**)&off, g_off);
    cudaGetSymbolAddress((void**)&cur, g_cur);
    cudaGetSymbolAddress((void**)&se, g_se);

    const int eb = (E + 255) / 256;
    const int nb = (N + 255) / 256;
    const int gemm_blocks = (N + 127) / 128;
    const int cls_blocks = (N + 31) / 32;
    const int agg_blocks = (N * 32 + 255) / 256;   // warp per node

    // ---- One-time counting sort of edges by dst ----
    zero_int<<<nb, 256>>>(deg, N);
    count_deg<<<eb, 256>>>(ei, deg, E);
    scan1<<<SCAN_NB, SCAN_B>>>(deg, excl, btot, N);
    scan2<<<1, 256>>>(btot, SCAN_NB);
    scan3<<<SCAN_NB, SCAN_B>>>(excl, btot, off, cur, N, E);
    scatter_edges<<<eb, 256>>>(ei, ea, cur, se, E);

    // ---- Layer 1 ----
    aggregate<<<agg_blocks, 256>>>((const float4*)x, se, off, eps1, We1, be1,
                                   (float4*)A, N);
    gemm_bf<true><<<gemm_blocks, 256>>>(A, W11, b11, B, N);
    gemm_bf<true><<<gemm_blocks, 256>>>(B, W12, b12, C, N);   // outer relu fused

    // ---- Layer 2 ----
    aggregate<<<agg_blocks, 256>>>((const float4*)C, se, off, eps2, We2, be2,
                                   (float4*)B, N);
    gemm_bf<true><<<gemm_blocks, 256>>>(B, W21, b21, A, N);
    gemm_bf<true><<<gemm_blocks, 256>>>(A, W22, b22, B, N);   // outer relu fused

    // ---- Classifier + log_softmax ----
    classify_lsm<<<cls_blocks, 256>>>(B, Wl, bl, out, N);
}